// round 5
// baseline (speedup 1.0000x reference)
#include <cuda_runtime.h>
#include <math.h>

#define NB 8
#define NH 8
#define NS 6144
#define NSM1 6143
#define NDM 512
#define NDK 64
#define NWN 6113
#define NM 32
#define NWC 12

typedef unsigned long long u64;
__device__ __forceinline__ u64 ffma2(u64 a, u64 b, u64 c) {
    u64 d; asm("fma.rn.f32x2 %0,%1,%2,%3;" : "=l"(d) : "l"(a), "l"(b), "l"(c)); return d;
}
__device__ __forceinline__ float2 upk(u64 v) {
    float2 r; asm("mov.b64 {%0,%1},%2;" : "=f"(r.x), "=f"(r.y) : "l"(v)); return r;
}

__device__ float g_WkM[512 * 512];
__device__ float g_WqM[512 * 512];
__device__ float g_WvM[512 * 512];
__device__ float g_WOMt[512 * 512];
__device__ float g_Khat[(size_t)NB * NH * NS * NDK];
__device__ float g_Qhat[NB * NH * NM * NDK];
__device__ float g_qa[NB * NH * 32];
__device__ float g_qp[NB * NH * 16];
__device__ float g_tn[(size_t)NB * NH * NS];
__device__ float g_d2[(size_t)NB * NH * NS];
__device__ float g_d3[(size_t)NB * NH * NS];
__device__ float g_attn[(size_t)NB * NH * NS];
__device__ float g_alast[NB * NH];
__device__ float g_ctxp[NB * NWC * NH * NDM];
__device__ float g_hist[NB * NH * NDK];
__device__ float g_GI[31 * NB * 192];
__device__ float g_res[NB * NDK];

// ---- masked weights ----
__global__ void prep_kernel(const float* __restrict__ Wk, const float* __restrict__ Wq,
                            const float* __restrict__ Wv, const float* __restrict__ WO,
                            const int* __restrict__ G) {
    int i = blockIdx.x * blockDim.x + threadIdx.x;
    if (i >= 512 * 512) return;
    int row = i >> 9, d = i & 511;
    float gm = (float)G[(row & 63) * 64 + (d & 63)];
    g_WkM[i] = Wk[i] * gm;
    g_WqM[i] = Wq[i] * gm;
    g_WvM[i] = Wv[i] * gm;
    float gm2 = (float)G[(d & 63) * 64 + (row & 63)];
    g_WOMt[i] = WO[d * 512 + row] * gm2;  // [e][d] = WO[d][e]*mask
}

// ---- K projection + bias + l2norm : grid(96,8,8), 256 thr, 64x64 tile, FFMA2 ----
__global__ void __launch_bounds__(256) kproj_kernel(const float* __restrict__ mem,
                                                    const float* __restrict__ xpre,
                                                    const float* __restrict__ bk) {
    __shared__ __align__(16) float sm[32 * 68 + 32 * 136];
    float* As = sm;            // [k=32][row=64] stride 68
    float* Bs2 = sm + 32 * 68; // [k=32][2*col=128] stride 136, duplicated
    int s0 = blockIdx.x * 64, h = blockIdx.y, b = blockIdx.z;
    int tid = threadIdx.x;
    int ty = tid >> 4, tx = tid & 15;
    int lr = tid >> 2, lc = (tid & 3) * 8;
    u64 acc2[2][4] = {};
    const float* wbase = g_WkM + (h * 64) * 512;
    for (int d0 = 0; d0 < 512; d0 += 32) {
        __syncthreads();
        int s = s0 + lr;
        const float* src = (s < NSM1) ? (mem + ((size_t)b * NSM1 + s) * 512 + d0 + lc)
                                      : (xpre + b * 512 + d0 + lc);
        float4 v0 = *(const float4*)(src);
        float4 v1 = *(const float4*)(src + 4);
        As[(lc + 0) * 68 + lr] = v0.x; As[(lc + 1) * 68 + lr] = v0.y;
        As[(lc + 2) * 68 + lr] = v0.z; As[(lc + 3) * 68 + lr] = v0.w;
        As[(lc + 4) * 68 + lr] = v1.x; As[(lc + 5) * 68 + lr] = v1.y;
        As[(lc + 6) * 68 + lr] = v1.z; As[(lc + 7) * 68 + lr] = v1.w;
        const float* wsrc = wbase + lr * 512 + d0 + lc;
        float4 w0 = *(const float4*)(wsrc);
        float4 w1 = *(const float4*)(wsrc + 4);
        float wv[8] = {w0.x, w0.y, w0.z, w0.w, w1.x, w1.y, w1.z, w1.w};
#pragma unroll
        for (int i = 0; i < 8; i++)
            *(float2*)&Bs2[(lc + i) * 136 + 2 * lr] = make_float2(wv[i], wv[i]);
        __syncthreads();
#pragma unroll
        for (int kk = 0; kk < 32; kk++) {
            ulonglong2 a2 = *(const ulonglong2*)&As[kk * 68 + ty * 4];
            ulonglong2 bA = *(const ulonglong2*)&Bs2[kk * 136 + tx * 8];
            ulonglong2 bB = *(const ulonglong2*)&Bs2[kk * 136 + tx * 8 + 4];
            acc2[0][0] = ffma2(a2.x, bA.x, acc2[0][0]);
            acc2[0][1] = ffma2(a2.x, bA.y, acc2[0][1]);
            acc2[0][2] = ffma2(a2.x, bB.x, acc2[0][2]);
            acc2[0][3] = ffma2(a2.x, bB.y, acc2[0][3]);
            acc2[1][0] = ffma2(a2.y, bA.x, acc2[1][0]);
            acc2[1][1] = ffma2(a2.y, bA.y, acc2[1][1]);
            acc2[1][2] = ffma2(a2.y, bB.x, acc2[1][2]);
            acc2[1][3] = ffma2(a2.y, bB.y, acc2[1][3]);
        }
    }
    __syncthreads();
    float* Ct = sm;  // 64x65
#pragma unroll
    for (int p = 0; p < 2; p++)
#pragma unroll
        for (int c = 0; c < 4; c++) {
            float2 f = upk(acc2[p][c]);
            float bias = bk[h * 64 + tx * 4 + c];
            Ct[(ty * 4 + 2 * p + 0) * 65 + tx * 4 + c] = f.x + bias;
            Ct[(ty * 4 + 2 * p + 1) * 65 + tx * 4 + c] = f.y + bias;
        }
    __syncthreads();
    int warp = tid >> 5, lane = tid & 31;
    for (int rr = warp; rr < 64; rr += 8) {
        float v0 = Ct[rr * 65 + lane], v1 = Ct[rr * 65 + lane + 32];
        float ss = v0 * v0 + v1 * v1;
#pragma unroll
        for (int o = 16; o; o >>= 1) ss += __shfl_xor_sync(0xffffffffu, ss, o);
        float inv = 1.0f / fmaxf(sqrtf(ss), 1e-12f);
        size_t base = (((size_t)(b * 8 + h)) * NS + s0 + rr) * 64;
        g_Khat[base + lane] = v0 * inv;
        g_Khat[base + lane + 32] = v1 * inv;
    }
}

// ---- Q projection (last 32 rows) : grid(8h,8b), 256 thr ----
__global__ void __launch_bounds__(256) qproj_kernel(const float* __restrict__ mem,
                                                    const float* __restrict__ xpre,
                                                    const float* __restrict__ bq) {
    int h = blockIdx.x, b = blockIdx.y, tid = threadIdx.x;
    int m = tid >> 3, cg = (tid & 7) * 8;
    float acc[8] = {};
    int s = 6112 + m;
    const float* xr = (s < NSM1) ? (mem + ((size_t)b * NSM1 + s) * 512) : (xpre + b * 512);
    const float* wb = g_WqM + (h * 64 + cg) * 512;
    for (int d = 0; d < 512; d += 4) {
        float4 xv = *(const float4*)(xr + d);
#pragma unroll
        for (int c = 0; c < 8; c++) {
            float4 wv = *(const float4*)(wb + c * 512 + d);
            acc[c] += xv.x * wv.x + xv.y * wv.y + xv.z * wv.z + xv.w * wv.w;
        }
    }
    __shared__ float qs[32 * 65];
#pragma unroll
    for (int c = 0; c < 8; c++) qs[m * 65 + cg + c] = acc[c] + bq[h * 64 + cg + c];
    __syncthreads();
    if (tid < 32) {
        float ss = 0.f;
        for (int c = 0; c < 64; c++) { float v = qs[tid * 65 + c]; ss += v * v; }
        float inv = 1.f / fmaxf(sqrtf(ss), 1e-12f);
        float* dst = g_Qhat + ((b * 8 + h) * 32 + tid) * 64;
        for (int c = 0; c < 64; c++) dst[c] = qs[tid * 65 + c] * inv;
    }
}

// ---- qa_last, qp_last ----
__global__ void qa_kernel(const float* __restrict__ aux, const float* __restrict__ Wqa,
                          const float* __restrict__ bqa) {
    int b = blockIdx.x, tid = threadIdx.x;
    int h = tid >> 5, c = tid & 31;
    const float* row = aux + ((size_t)b * NS + NS - 1) * 256;
    const float* wr = Wqa + (h * 32 + c) * 256;
    float acc = bqa[h * 32 + c];
    for (int a = 0; a < 256; a += 4) {
        float4 xv = *(const float4*)(row + a);
        float4 wv = *(const float4*)(wr + a);
        acc += xv.x * wv.x + xv.y * wv.y + xv.z * wv.z + xv.w * wv.w;
    }
    float ss = acc * acc;
#pragma unroll
    for (int o = 16; o; o >>= 1) ss += __shfl_xor_sync(0xffffffffu, ss, o);
    g_qa[(b * 8 + h) * 32 + c] = acc / fmaxf(sqrtf(ss), 1e-12f);
}

__global__ void qp_kernel(const float* __restrict__ pos, const float* __restrict__ Wqp,
                          const float* __restrict__ bqp) {
    int b = blockIdx.x, tid = threadIdx.x;
    int h = tid >> 4, c = tid & 15;
    const float* row = pos + ((size_t)b * NS + NS - 1) * 128;
    const float* wr = Wqp + (h * 16 + c) * 128;
    float acc = bqp[h * 16 + c];
    for (int a = 0; a < 128; a += 4) {
        float4 xv = *(const float4*)(row + a);
        float4 wv = *(const float4*)(wr + a);
        acc += xv.x * wv.x + xv.y * wv.y + xv.z * wv.z + xv.w * wv.w;
    }
    float ss = acc * acc;
#pragma unroll
    for (int o = 8; o; o >>= 1) ss += __shfl_xor_sync(0xffffffffu, ss, o);
    g_qp[(b * 8 + h) * 16 + c] = acc / fmaxf(sqrtf(ss), 1e-12f);
}

// ---- dot2: KA proj + norm + dot qa : grid(96,8,8), 256 thr, FFMA2 ----
__global__ void __launch_bounds__(256) dot2_kernel(const float* __restrict__ aux,
                                                   const float* __restrict__ Wka,
                                                   const float* __restrict__ bka) {
    __shared__ __align__(16) float sm[32 * 68 + 32 * 72];
    float* As = sm;
    float* Bs2 = sm + 32 * 68;  // [k][2*col=64] stride 72, duplicated
    int j0 = blockIdx.x * 64, h = blockIdx.y, b = blockIdx.z;
    int tid = threadIdx.x;
    int ty = tid >> 4, tx = tid & 15;
    int lr = tid >> 2, lc = (tid & 3) * 8;
    int wr = tid >> 3, wc = (tid & 7) * 4;
    u64 acc2[2][2] = {};
    for (int d0 = 0; d0 < 256; d0 += 32) {
        __syncthreads();
        int j = j0 + lr;
        float4 v0 = make_float4(0.f, 0.f, 0.f, 0.f), v1 = v0;
        if (j < NWN) {
            const float* src = aux + ((size_t)b * NS + 31 + j) * 256 + d0 + lc;
            v0 = *(const float4*)(src);
            v1 = *(const float4*)(src + 4);
        }
        As[(lc + 0) * 68 + lr] = v0.x; As[(lc + 1) * 68 + lr] = v0.y;
        As[(lc + 2) * 68 + lr] = v0.z; As[(lc + 3) * 68 + lr] = v0.w;
        As[(lc + 4) * 68 + lr] = v1.x; As[(lc + 5) * 68 + lr] = v1.y;
        As[(lc + 6) * 68 + lr] = v1.z; As[(lc + 7) * 68 + lr] = v1.w;
        float4 wv = *(const float4*)(Wka + (h * 32 + wr) * 256 + d0 + wc);
        *(float2*)&Bs2[(wc + 0) * 72 + 2 * wr] = make_float2(wv.x, wv.x);
        *(float2*)&Bs2[(wc + 1) * 72 + 2 * wr] = make_float2(wv.y, wv.y);
        *(float2*)&Bs2[(wc + 2) * 72 + 2 * wr] = make_float2(wv.z, wv.z);
        *(float2*)&Bs2[(wc + 3) * 72 + 2 * wr] = make_float2(wv.w, wv.w);
        __syncthreads();
#pragma unroll
        for (int kk = 0; kk < 32; kk++) {
            ulonglong2 a2 = *(const ulonglong2*)&As[kk * 68 + ty * 4];
            ulonglong2 bb = *(const ulonglong2*)&Bs2[kk * 72 + tx * 4];
            acc2[0][0] = ffma2(a2.x, bb.x, acc2[0][0]);
            acc2[0][1] = ffma2(a2.x, bb.y, acc2[0][1]);
            acc2[1][0] = ffma2(a2.y, bb.x, acc2[1][0]);
            acc2[1][1] = ffma2(a2.y, bb.y, acc2[1][1]);
        }
    }
    __syncthreads();
    float* Ct = sm;  // 64x33
#pragma unroll
    for (int p = 0; p < 2; p++)
#pragma unroll
        for (int c = 0; c < 2; c++) {
            float2 f = upk(acc2[p][c]);
            float bias = bka[h * 32 + tx * 2 + c];
            Ct[(ty * 4 + 2 * p + 0) * 33 + tx * 2 + c] = f.x + bias;
            Ct[(ty * 4 + 2 * p + 1) * 33 + tx * 2 + c] = f.y + bias;
        }
    __syncthreads();
    if (tid < 64) {
        int j = j0 + tid;
        if (j < NWN) {
            const float* qa = g_qa + (b * 8 + h) * 32;
            float ss = 0.f, dt = 0.f;
            for (int c = 0; c < 32; c++) {
                float v = Ct[tid * 33 + c];
                ss += v * v; dt += qa[c] * v;
            }
            g_d2[(size_t)(b * 8 + h) * NS + j] = dt / fmaxf(sqrtf(ss), 1e-12f);
        }
    }
}

// ---- dot3: KP proj + norm + dot qp : grid(96,8,8), 128 thr, FFMA2 ----
__global__ void __launch_bounds__(128) dot3_kernel(const float* __restrict__ pos,
                                                   const float* __restrict__ Wkp,
                                                   const float* __restrict__ bkp) {
    __shared__ __align__(16) float sm[32 * 68 + 32 * 40];
    float* As = sm;
    float* Bs2 = sm + 32 * 68;  // [k][2*col=32] stride 40, duplicated
    int j0 = blockIdx.x * 64, h = blockIdx.y, b = blockIdx.z;
    int tid = threadIdx.x;
    int ty = tid >> 3, tx = tid & 7;
    u64 acc2[2][2] = {};
    for (int d0 = 0; d0 < 128; d0 += 32) {
        __syncthreads();
        for (int v = tid; v < 512; v += 128) {
            int rr = v >> 3, c4 = (v & 7) * 4;
            int j = j0 + rr;
            float4 val = make_float4(0.f, 0.f, 0.f, 0.f);
            if (j < NWN) val = *(const float4*)(pos + ((size_t)b * NS + 31 + j) * 128 + d0 + c4);
            As[(c4 + 0) * 68 + rr] = val.x; As[(c4 + 1) * 68 + rr] = val.y;
            As[(c4 + 2) * 68 + rr] = val.z; As[(c4 + 3) * 68 + rr] = val.w;
        }
        {
            int col = tid & 15, wc = (tid >> 4) * 4;
            float4 wv = *(const float4*)(Wkp + (h * 16 + col) * 128 + d0 + wc);
            *(float2*)&Bs2[(wc + 0) * 40 + 2 * col] = make_float2(wv.x, wv.x);
            *(float2*)&Bs2[(wc + 1) * 40 + 2 * col] = make_float2(wv.y, wv.y);
            *(float2*)&Bs2[(wc + 2) * 40 + 2 * col] = make_float2(wv.z, wv.z);
            *(float2*)&Bs2[(wc + 3) * 40 + 2 * col] = make_float2(wv.w, wv.w);
        }
        __syncthreads();
#pragma unroll
        for (int kk = 0; kk < 32; kk++) {
            ulonglong2 a2 = *(const ulonglong2*)&As[kk * 68 + ty * 4];
            ulonglong2 bb = *(const ulonglong2*)&Bs2[kk * 40 + tx * 4];
            acc2[0][0] = ffma2(a2.x, bb.x, acc2[0][0]);
            acc2[0][1] = ffma2(a2.x, bb.y, acc2[0][1]);
            acc2[1][0] = ffma2(a2.y, bb.x, acc2[1][0]);
            acc2[1][1] = ffma2(a2.y, bb.y, acc2[1][1]);
        }
    }
    __syncthreads();
    float* Ct = sm;  // 64x17
#pragma unroll
    for (int p = 0; p < 2; p++)
#pragma unroll
        for (int c = 0; c < 2; c++) {
            float2 f = upk(acc2[p][c]);
            float bias = bkp[h * 16 + tx * 2 + c];
            Ct[(ty * 4 + 2 * p + 0) * 17 + tx * 2 + c] = f.x + bias;
            Ct[(ty * 4 + 2 * p + 1) * 17 + tx * 2 + c] = f.y + bias;
        }
    __syncthreads();
    if (tid < 64) {
        int j = j0 + tid;
        if (j < NWN) {
            const float* qp = g_qp + (b * 8 + h) * 16;
            float ss = 0.f, dt = 0.f;
            for (int c = 0; c < 16; c++) {
                float v = Ct[tid * 17 + c];
                ss += v * v; dt += qp[c] * v;
            }
            g_d3[(size_t)(b * 8 + h) * NS + j] = dt / fmaxf(sqrtf(ss), 1e-12f);
        }
    }
}

// ---- tn: banded correlation : grid(48,8,8), 128 thr, FFMA2 ----
__global__ void __launch_bounds__(128) tn_kernel() {
    int j0 = blockIdx.x * 128, h = blockIdx.y, b = blockIdx.z;
    int bh = b * 8 + h, tid = threadIdx.x;
    __shared__ __align__(16) float qs[32 * 64];
    __shared__ __align__(16) float Ks[159 * 36];
    for (int u = tid; u < 512; u += 128)
        ((float4*)qs)[u] = ((const float4*)(g_Qhat + bh * 2048))[u];
    u64 acc2a = 0, acc2b = 0;
    const float* kb = g_Khat + (size_t)bh * NS * 64;
    for (int p = 0; p < 2; p++) {
        __syncthreads();
        for (int v = tid; v < 159 * 8; v += 128) {
            int u = v >> 3, c4 = (v & 7) * 4;
            int s = j0 + u;
            float4 val = make_float4(0.f, 0.f, 0.f, 0.f);
            if (s < NS) val = *(const float4*)(kb + (size_t)s * 64 + p * 32 + c4);
            *(float4*)&Ks[u * 36 + c4] = val;
        }
        __syncthreads();
#pragma unroll 4
        for (int m = 0; m < 32; m++) {
            const float* qrow = qs + m * 64 + p * 32;
            const float* krow = Ks + (tid + m) * 36;
#pragma unroll
            for (int c = 0; c < 8; c++) {
                ulonglong2 kv = *(const ulonglong2*)(krow + c * 4);
                ulonglong2 qv = *(const ulonglong2*)(qrow + c * 4);
                acc2a = ffma2(qv.x, kv.x, acc2a);
                acc2b = ffma2(qv.y, kv.y, acc2b);
            }
        }
    }
    float2 fa = upk(acc2a), fb = upk(acc2b);
    float acc = fa.x + fa.y + fb.x + fb.y;
    int j = j0 + tid;
    if (j < NWN) g_tn[(size_t)bh * NS + j] = acc * (1.0f / 32.0f);
}

// ---- softmax over Wn : grid(64), 256 thr ----
__global__ void __launch_bounds__(256) softmax_kernel(const float* __restrict__ w,
                                                      const float* __restrict__ wa,
                                                      const float* __restrict__ wp) {
    int bh = blockIdx.x, tid = threadIdx.x;
    float w0 = w[0], w1 = wa[0], w2 = wp[0];
    size_t base = (size_t)bh * NS;
    __shared__ float red[256];
    float mx = -1e30f;
    for (int j = tid; j < NWN; j += 256) {
        float z = w0 * g_tn[base + j] + w1 * g_d2[base + j] + w2 * g_d3[base + j];
        g_attn[base + j] = z;
        mx = fmaxf(mx, z);
    }
    red[tid] = mx; __syncthreads();
    for (int o = 128; o; o >>= 1) { if (tid < o) red[tid] = fmaxf(red[tid], red[tid + o]); __syncthreads(); }
    mx = red[0]; __syncthreads();
    float sum = 0.f;
    for (int j = tid; j < NWN; j += 256) {
        float e = __expf(g_attn[base + j] - mx);
        g_attn[base + j] = e;
        sum += e;
    }
    red[tid] = sum; __syncthreads();
    for (int o = 128; o; o >>= 1) { if (tid < o) red[tid] += red[tid + o]; __syncthreads(); }
    float inv = 1.f / red[0];
    __syncthreads();
    for (int j = tid; j < NWN; j += 256) g_attn[base + j] *= inv;
    __syncthreads();
    if (tid == 0) g_alast[bh] = g_attn[base + NWN - 1];
}

// ---- ctx partial: attn-weighted sum of x rows : grid(12,8), 512 thr ----
__global__ void __launch_bounds__(512) ctxp_kernel(const float* __restrict__ mem) {
    int wc = blockIdx.x, b = blockIdx.y, tid = threadIdx.x;
    __shared__ float at[8 * 512];
    int w0 = wc * 512;
    for (int u = tid; u < 4096; u += 512) {
        int h = u >> 9, ww = u & 511;
        int w = w0 + ww;
        at[h * 512 + ww] = (w < NWN - 1) ? g_attn[(size_t)(b * 8 + h) * NS + w] : 0.f;
    }
    __syncthreads();
    float acc[8] = {};
    const float* mb = mem + ((size_t)b * NSM1 + 31 + w0) * 512 + tid;
    int wlim = (NWN - 1) - w0; if (wlim > 512) wlim = 512;
    for (int ww = 0; ww < wlim; ww++) {
        float x = mb[(size_t)ww * 512];
#pragma unroll
        for (int h2 = 0; h2 < 8; h2++) acc[h2] += at[h2 * 512 + ww] * x;
    }
#pragma unroll
    for (int h2 = 0; h2 < 8; h2++)
        g_ctxp[(((b * NWC + wc) * 8 + h2) << 9) + tid] = acc[h2];
}

// ---- hist: reduce ctx partials, project through WvM : grid(8b,8h), 256 thr ----
__global__ void __launch_bounds__(256) hist_kernel(const float* __restrict__ bv) {
    int b = blockIdx.x, h = blockIdx.y, tid = threadIdx.x;
    __shared__ float ctxs[512];
    __shared__ float red[256];
    for (int d = tid; d < 512; d += 256) {
        float s = 0.f;
        for (int wc = 0; wc < NWC; wc++)
            s += g_ctxp[(((b * NWC + wc) * 8 + h) << 9) + d];
        ctxs[d] = s;
    }
    __syncthreads();
    int kk = tid >> 2, q = (tid & 3) * 128;
    const float* wr = g_WvM + (h * 64 + kk) * 512 + q;
    float acc = 0.f;
    for (int d = 0; d < 128; d += 4) {
        float4 wv = *(const float4*)(wr + d);
        acc += wv.x * ctxs[q + d] + wv.y * ctxs[q + d + 1] + wv.z * ctxs[q + d + 2] + wv.w * ctxs[q + d + 3];
    }
    red[tid] = acc;
    __syncthreads();
    if (tid < 64) {
        float a1 = 1.0f - g_alast[b * 8 + h];
        float s = red[tid * 4] + red[tid * 4 + 1] + red[tid * 4 + 2] + red[tid * 4 + 3];
        g_hist[(b * 8 + h) * 64 + tid] = s + bv[h * 64 + tid] * a1;
    }
}

// ---- GRU gi precompute : grid(31,8), 192 thr ----
__global__ void gi_kernel(const float* __restrict__ mem, const float* __restrict__ W_ih,
                          const float* __restrict__ b_ih) {
    int t = blockIdx.x, b = blockIdx.y, j = threadIdx.x;
    const float* xr = mem + ((size_t)b * NSM1 + 6112 + t) * 512;
    const float* wr = W_ih + j * 512;
    float acc = b_ih[j];
    for (int d = 0; d < 512; d += 4) {
        float4 xv = *(const float4*)(xr + d);
        float4 wv = *(const float4*)(wr + d);
        acc += xv.x * wv.x + xv.y * wv.y + xv.z * wv.z + xv.w * wv.w;
    }
    g_GI[(t * 8 + b) * 192 + j] = acc;
}

// ---- GRU scan : 1 block, 512 thr ----
__global__ void __launch_bounds__(512) scan_kernel(const float* __restrict__ W_hh,
                                                   const float* __restrict__ b_hh) {
    int tid = threadIdx.x;
    int b = tid >> 6, kk = tid & 63;
    __shared__ float hs[8 * 64];
    hs[tid] = 0.f;
    __syncthreads();
    float bhr = b_hh[kk], bhz = b_hh[64 + kk], bhn = b_hh[128 + kk];
    const float* wr = W_hh + kk * 64;
    const float* wz = W_hh + (64 + kk) * 64;
    const float* wn = W_hh + (128 + kk) * 64;
    for (int t = 0; t < 31; t++) {
        float hr = bhr, hz = bhz, hn = bhn;
        const float* hb = hs + b * 64;
#pragma unroll 8
        for (int e = 0; e < 64; e++) {
            float he = hb[e];
            hr += wr[e] * he; hz += wz[e] * he; hn += wn[e] * he;
        }
        const float* gi = g_GI + (t * 8 + b) * 192;
        float r = 1.f / (1.f + __expf(-(gi[kk] + hr)));
        float z = 1.f / (1.f + __expf(-(gi[64 + kk] + hz)));
        float nst = tanhf(gi[128 + kk] + r * hn);
        float hold = hb[kk];
        float hnew = (1.f - z) * nst + z * hold;
        __syncthreads();
        hs[tid] = hnew;
        __syncthreads();
    }
    g_res[tid] = hs[tid];
}

// ---- final output : grid(8), 512 thr ----
__global__ void __launch_bounds__(512) final_kernel(const float* __restrict__ xpre,
                                                    const float* __restrict__ bO,
                                                    float* __restrict__ out) {
    int b = blockIdx.x, tid = threadIdx.x;
    __shared__ float det[512];
    {
        int h = tid >> 6, kk = tid & 63;
        det[tid] = g_hist[(b * 8 + h) * 64 + kk] + g_alast[b * 8 + h] * g_res[b * 64 + kk];
    }
    __syncthreads();
    float acc = 0.f;
    for (int e = 0; e < 512; e++) acc += det[e] * g_WOMt[e * 512 + tid];
    out[b * 512 + tid] = xpre[b * 512 + tid] + acc + bO[tid];
}

extern "C" void kernel_launch(void* const* d_in, const int* in_sizes, int n_in,
                              void* d_out, int out_size) {
    const float* mem  = (const float*)d_in[0];
    const float* xpre = (const float*)d_in[1];
    const float* aux  = (const float*)d_in[2];
    const float* pos  = (const float*)d_in[3];
    const float* Wq   = (const float*)d_in[4];
    const float* bq   = (const float*)d_in[5];
    const float* Wk   = (const float*)d_in[6];
    const float* bk   = (const float*)d_in[7];
    const float* Wv   = (const float*)d_in[8];
    const float* bv   = (const float*)d_in[9];
    const float* Wqa  = (const float*)d_in[10];
    const float* bqa  = (const float*)d_in[11];
    const float* Wka  = (const float*)d_in[12];
    const float* bka  = (const float*)d_in[13];
    const float* Wqp  = (const float*)d_in[14];
    const float* bqp  = (const float*)d_in[15];
    const float* Wkp  = (const float*)d_in[16];
    const float* bkp  = (const float*)d_in[17];
    const float* W_ih = (const float*)d_in[18];
    const float* W_hh = (const float*)d_in[19];
    const float* b_ih = (const float*)d_in[20];
    const float* b_hh = (const float*)d_in[21];
    const float* WO   = (const float*)d_in[22];
    const float* bO   = (const float*)d_in[23];
    const float* w    = (const float*)d_in[24];
    const float* wa   = (const float*)d_in[25];
    const float* wp   = (const float*)d_in[26];
    const int*   G    = (const int*)d_in[27];
    float* out = (float*)d_out;

    prep_kernel<<<(512 * 512 + 255) / 256, 256>>>(Wk, Wq, Wv, WO, G);
    kproj_kernel<<<dim3(96, 8, 8), 256>>>(mem, xpre, bk);
    qproj_kernel<<<dim3(8, 8), 256>>>(mem, xpre, bq);
    qa_kernel<<<8, 256>>>(aux, Wqa, bqa);
    qp_kernel<<<8, 128>>>(pos, Wqp, bqp);
    dot2_kernel<<<dim3(96, 8, 8), 256>>>(aux, Wka, bka);
    dot3_kernel<<<dim3(96, 8, 8), 128>>>(pos, Wkp, bkp);
    tn_kernel<<<dim3(48, 8, 8), 128>>>();
    softmax_kernel<<<64, 256>>>(w, wa, wp);
    ctxp_kernel<<<dim3(NWC, 8), 512>>>(mem);
    hist_kernel<<<dim3(8, 8), 256>>>(bv);
    gi_kernel<<<dim3(31, 8), 192>>>(mem, W_ih, b_ih);
    scan_kernel<<<1, 512>>>(W_hh, b_hh);
    final_kernel<<<8, 512>>>(xpre, bO, out);
}

// round 7
// speedup vs baseline: 1.5820x; 1.5820x over previous
#include <cuda_runtime.h>
#include <math.h>

#define NB 8
#define NH 8
#define NS 6144
#define NSM1 6143
#define NDM 512
#define NDK 64
#define NWN 6113
#define NM 32
#define NWC 12

__device__ float g_WkM[512 * 512];
__device__ float g_WqM[512 * 512];
__device__ float g_WvM[512 * 512];
__device__ float g_WOMt[512 * 512];
__device__ float g_Khat[(size_t)NB * NH * NS * NDK];
__device__ float g_Qhat[NB * NH * NM * NDK];
__device__ float g_qa[NB * NH * 32];
__device__ float g_qp[NB * NH * 16];
__device__ float g_tn[(size_t)NB * NH * NS];
__device__ float g_d2[(size_t)NB * NH * NS];
__device__ float g_d3[(size_t)NB * NH * NS];
__device__ float g_attn[(size_t)NB * NH * NS];
__device__ float g_alast[NB * NH];
__device__ float g_ctxp[NB * NWC * NH * NDM];
__device__ float g_hist[NB * NH * NDK];
__device__ float g_GI[31 * NB * 192];
__device__ float g_res[NB * NDK];

// ---- masked weights ----
__global__ void prep_kernel(const float* __restrict__ Wk, const float* __restrict__ Wq,
                            const float* __restrict__ Wv, const float* __restrict__ WO,
                            const int* __restrict__ G) {
    int i = blockIdx.x * blockDim.x + threadIdx.x;
    if (i >= 512 * 512) return;
    int row = i >> 9, d = i & 511;
    float gm = (float)G[(row & 63) * 64 + (d & 63)];
    g_WkM[i] = Wk[i] * gm;
    g_WqM[i] = Wq[i] * gm;
    g_WvM[i] = Wv[i] * gm;
    float gm2 = (float)G[(d & 63) * 64 + (row & 63)];
    g_WOMt[i] = WO[d * 512 + row] * gm2;  // [e][d] = WO[d][e]*mask
}

// ---- K projection, all heads batched: grid(48,4,8), 256 thr, 128x128 tile ----
// C = x[6144x512] @ WkM^T ; epilogue: +bias, per-head l2norm, store Khat
__global__ void __launch_bounds__(256) kproj_kernel(const float* __restrict__ mem,
                                                    const float* __restrict__ xpre,
                                                    const float* __restrict__ bk) {
    __shared__ __align__(16) float As[32 * 132];  // [k][row]
    __shared__ __align__(16) float Bs[32 * 132];  // [k][n]
    int s0 = blockIdx.x * 128, n0 = blockIdx.y * 128, b = blockIdx.z;
    int tid = threadIdx.x;
    int ty = tid >> 4, tx = tid & 15;
    float acc[8][8] = {};
    for (int d0 = 0; d0 < 512; d0 += 32) {
        __syncthreads();
#pragma unroll
        for (int it = 0; it < 4; it++) {
            int idx = it * 256 + tid;
            int rr = idx >> 3, kq = (idx & 7) * 4;
            int s = s0 + rr;
            const float* src = (s < NSM1) ? (mem + ((size_t)b * NSM1 + s) * 512 + d0 + kq)
                                          : (xpre + b * 512 + d0 + kq);
            float4 v = *(const float4*)src;
            As[(kq + 0) * 132 + rr] = v.x; As[(kq + 1) * 132 + rr] = v.y;
            As[(kq + 2) * 132 + rr] = v.z; As[(kq + 3) * 132 + rr] = v.w;
            float4 wv = *(const float4*)(g_WkM + (size_t)(n0 + rr) * 512 + d0 + kq);
            Bs[(kq + 0) * 132 + rr] = wv.x; Bs[(kq + 1) * 132 + rr] = wv.y;
            Bs[(kq + 2) * 132 + rr] = wv.z; Bs[(kq + 3) * 132 + rr] = wv.w;
        }
        __syncthreads();
#pragma unroll
        for (int kk = 0; kk < 32; kk++) {
            float4 a0 = *(const float4*)&As[kk * 132 + ty * 4];
            float4 a1 = *(const float4*)&As[kk * 132 + 64 + ty * 4];
            float4 b0 = *(const float4*)&Bs[kk * 132 + tx * 4];
            float4 b1 = *(const float4*)&Bs[kk * 132 + 64 + tx * 4];
            float ar[8] = {a0.x, a0.y, a0.z, a0.w, a1.x, a1.y, a1.z, a1.w};
            float br[8] = {b0.x, b0.y, b0.z, b0.w, b1.x, b1.y, b1.z, b1.w};
#pragma unroll
            for (int i = 0; i < 8; i++)
#pragma unroll
                for (int j = 0; j < 8; j++) acc[i][j] += ar[i] * br[j];
        }
    }
    // epilogue: bias + per-head l2norm. cols j<4 => head h0=n0/64 (+0), j>=4 => h0+1.
    float bias[8];
#pragma unroll
    for (int j = 0; j < 4; j++) {
        bias[j] = bk[n0 + tx * 4 + j];
        bias[4 + j] = bk[n0 + 64 + tx * 4 + j];
    }
    int h0 = n0 >> 6;
#pragma unroll
    for (int i = 0; i < 8; i++) {
        int r = (i < 4) ? (ty * 4 + i) : (64 + ty * 4 + (i - 4));
        int s = s0 + r;
        float v[8];
        float ss0 = 0.f, ss1 = 0.f;
#pragma unroll
        for (int j = 0; j < 8; j++) {
            v[j] = acc[i][j] + bias[j];
            if (j < 4) ss0 += v[j] * v[j]; else ss1 += v[j] * v[j];
        }
#pragma unroll
        for (int o = 8; o; o >>= 1) {
            ss0 += __shfl_xor_sync(0xffffffffu, ss0, o);
            ss1 += __shfl_xor_sync(0xffffffffu, ss1, o);
        }
        float i0 = 1.0f / fmaxf(sqrtf(ss0), 1e-12f);
        float i1 = 1.0f / fmaxf(sqrtf(ss1), 1e-12f);
        float* d0p = g_Khat + (((size_t)(b * 8 + h0)) * NS + s) * 64 + tx * 4;
        float* d1p = g_Khat + (((size_t)(b * 8 + h0 + 1)) * NS + s) * 64 + tx * 4;
        *(float4*)d0p = make_float4(v[0] * i0, v[1] * i0, v[2] * i0, v[3] * i0);
        *(float4*)d1p = make_float4(v[4] * i1, v[5] * i1, v[6] * i1, v[7] * i1);
    }
}

// ---- Q projection (last 32 rows) : grid(8h,8b), 256 thr ----
__global__ void __launch_bounds__(256) qproj_kernel(const float* __restrict__ mem,
                                                    const float* __restrict__ xpre,
                                                    const float* __restrict__ bq) {
    int h = blockIdx.x, b = blockIdx.y, tid = threadIdx.x;
    int m = tid >> 3, cg = (tid & 7) * 8;
    float acc[8] = {};
    int s = 6112 + m;
    const float* xr = (s < NSM1) ? (mem + ((size_t)b * NSM1 + s) * 512) : (xpre + b * 512);
    const float* wb = g_WqM + (h * 64 + cg) * 512;
    for (int d = 0; d < 512; d += 4) {
        float4 xv = *(const float4*)(xr + d);
#pragma unroll
        for (int c = 0; c < 8; c++) {
            float4 wv = *(const float4*)(wb + c * 512 + d);
            acc[c] += xv.x * wv.x + xv.y * wv.y + xv.z * wv.z + xv.w * wv.w;
        }
    }
    __shared__ float qs[32 * 65];
#pragma unroll
    for (int c = 0; c < 8; c++) qs[m * 65 + cg + c] = acc[c] + bq[h * 64 + cg + c];
    __syncthreads();
    if (tid < 32) {
        float ss = 0.f;
        for (int c = 0; c < 64; c++) { float v = qs[tid * 65 + c]; ss += v * v; }
        float inv = 1.f / fmaxf(sqrtf(ss), 1e-12f);
        float* dst = g_Qhat + ((b * 8 + h) * 32 + tid) * 64;
        for (int c = 0; c < 64; c++) dst[c] = qs[tid * 65 + c] * inv;
    }
}

// ---- qa_last, qp_last ----
__global__ void qa_kernel(const float* __restrict__ aux, const float* __restrict__ Wqa,
                          const float* __restrict__ bqa) {
    int b = blockIdx.x, tid = threadIdx.x;
    int h = tid >> 5, c = tid & 31;
    const float* row = aux + ((size_t)b * NS + NS - 1) * 256;
    const float* wr = Wqa + (h * 32 + c) * 256;
    float acc = bqa[h * 32 + c];
    for (int a = 0; a < 256; a += 4) {
        float4 xv = *(const float4*)(row + a);
        float4 wv = *(const float4*)(wr + a);
        acc += xv.x * wv.x + xv.y * wv.y + xv.z * wv.z + xv.w * wv.w;
    }
    float ss = acc * acc;
#pragma unroll
    for (int o = 16; o; o >>= 1) ss += __shfl_xor_sync(0xffffffffu, ss, o);
    g_qa[(b * 8 + h) * 32 + c] = acc / fmaxf(sqrtf(ss), 1e-12f);
}

__global__ void qp_kernel(const float* __restrict__ pos, const float* __restrict__ Wqp,
                          const float* __restrict__ bqp) {
    int b = blockIdx.x, tid = threadIdx.x;
    int h = tid >> 4, c = tid & 15;
    const float* row = pos + ((size_t)b * NS + NS - 1) * 128;
    const float* wr = Wqp + (h * 16 + c) * 128;
    float acc = bqp[h * 16 + c];
    for (int a = 0; a < 128; a += 4) {
        float4 xv = *(const float4*)(row + a);
        float4 wv = *(const float4*)(wr + a);
        acc += xv.x * wv.x + xv.y * wv.y + xv.z * wv.z + xv.w * wv.w;
    }
    float ss = acc * acc;
#pragma unroll
    for (int o = 8; o; o >>= 1) ss += __shfl_xor_sync(0xffffffffu, ss, o);
    g_qp[(b * 8 + h) * 16 + c] = acc / fmaxf(sqrtf(ss), 1e-12f);
}

// ---- dot2: KA proj + norm + dot qa : grid(96,8,8), 256 thr ----
__global__ void __launch_bounds__(256) dot2_kernel(const float* __restrict__ aux,
                                                   const float* __restrict__ Wka,
                                                   const float* __restrict__ bka) {
    __shared__ float sm[32 * 68 + 32 * 36];
    float* As = sm;
    float* Bs = sm + 32 * 68;
    int j0 = blockIdx.x * 64, h = blockIdx.y, b = blockIdx.z;
    int tid = threadIdx.x;
    int ty = tid >> 4, tx = tid & 15;
    int lr = tid >> 2, lc = (tid & 3) * 8;
    int wr = tid >> 3, wc = (tid & 7) * 4;
    float acc[4][2] = {};
    for (int d0 = 0; d0 < 256; d0 += 32) {
        __syncthreads();
        int j = j0 + lr;
        float4 v0 = make_float4(0.f, 0.f, 0.f, 0.f), v1 = v0;
        if (j < NWN) {
            const float* src = aux + ((size_t)b * NS + 31 + j) * 256 + d0 + lc;
            v0 = *(const float4*)(src);
            v1 = *(const float4*)(src + 4);
        }
        As[(lc + 0) * 68 + lr] = v0.x; As[(lc + 1) * 68 + lr] = v0.y;
        As[(lc + 2) * 68 + lr] = v0.z; As[(lc + 3) * 68 + lr] = v0.w;
        As[(lc + 4) * 68 + lr] = v1.x; As[(lc + 5) * 68 + lr] = v1.y;
        As[(lc + 6) * 68 + lr] = v1.z; As[(lc + 7) * 68 + lr] = v1.w;
        float4 wv = *(const float4*)(Wka + (h * 32 + wr) * 256 + d0 + wc);
        Bs[(wc + 0) * 36 + wr] = wv.x; Bs[(wc + 1) * 36 + wr] = wv.y;
        Bs[(wc + 2) * 36 + wr] = wv.z; Bs[(wc + 3) * 36 + wr] = wv.w;
        __syncthreads();
#pragma unroll
        for (int kk = 0; kk < 32; kk++) {
            float4 av = *(const float4*)&As[kk * 68 + ty * 4];
            float b0 = Bs[kk * 36 + tx * 2], b1 = Bs[kk * 36 + tx * 2 + 1];
            acc[0][0] += av.x * b0; acc[0][1] += av.x * b1;
            acc[1][0] += av.y * b0; acc[1][1] += av.y * b1;
            acc[2][0] += av.z * b0; acc[2][1] += av.z * b1;
            acc[3][0] += av.w * b0; acc[3][1] += av.w * b1;
        }
    }
    __syncthreads();
    float* Ct = sm;  // 64x33
#pragma unroll
    for (int i = 0; i < 4; i++)
#pragma unroll
        for (int j = 0; j < 2; j++)
            Ct[(ty * 4 + i) * 33 + tx * 2 + j] = acc[i][j] + bka[h * 32 + tx * 2 + j];
    __syncthreads();
    if (tid < 64) {
        int j = j0 + tid;
        if (j < NWN) {
            const float* qa = g_qa + (b * 8 + h) * 32;
            float ss = 0.f, dt = 0.f;
            for (int c = 0; c < 32; c++) {
                float v = Ct[tid * 33 + c];
                ss += v * v; dt += qa[c] * v;
            }
            g_d2[(size_t)(b * 8 + h) * NS + j] = dt / fmaxf(sqrtf(ss), 1e-12f);
        }
    }
}

// ---- dot3: KP proj + norm + dot qp : grid(96,8,8), 128 thr ----
__global__ void __launch_bounds__(128) dot3_kernel(const float* __restrict__ pos,
                                                   const float* __restrict__ Wkp,
                                                   const float* __restrict__ bkp) {
    __shared__ float sm[32 * 68 + 32 * 20];
    float* As = sm;
    float* Bs = sm + 32 * 68;
    int j0 = blockIdx.x * 64, h = blockIdx.y, b = blockIdx.z;
    int tid = threadIdx.x;
    int ty = tid >> 3, tx = tid & 7;
    float acc[4][2] = {};
    for (int d0 = 0; d0 < 128; d0 += 32) {
        __syncthreads();
        for (int v = tid; v < 512; v += 128) {
            int rr = v >> 3, c4 = (v & 7) * 4;
            int j = j0 + rr;
            float4 val = make_float4(0.f, 0.f, 0.f, 0.f);
            if (j < NWN) val = *(const float4*)(pos + ((size_t)b * NS + 31 + j) * 128 + d0 + c4);
            As[(c4 + 0) * 68 + rr] = val.x; As[(c4 + 1) * 68 + rr] = val.y;
            As[(c4 + 2) * 68 + rr] = val.z; As[(c4 + 3) * 68 + rr] = val.w;
        }
        {
            int col = tid & 15, wc = (tid >> 4) * 4;
            float4 wv = *(const float4*)(Wkp + (h * 16 + col) * 128 + d0 + wc);
            Bs[(wc + 0) * 20 + col] = wv.x; Bs[(wc + 1) * 20 + col] = wv.y;
            Bs[(wc + 2) * 20 + col] = wv.z; Bs[(wc + 3) * 20 + col] = wv.w;
        }
        __syncthreads();
#pragma unroll
        for (int kk = 0; kk < 32; kk++) {
            float4 av = *(const float4*)&As[kk * 68 + ty * 4];
            float b0 = Bs[kk * 20 + tx * 2], b1 = Bs[kk * 20 + tx * 2 + 1];
            acc[0][0] += av.x * b0; acc[0][1] += av.x * b1;
            acc[1][0] += av.y * b0; acc[1][1] += av.y * b1;
            acc[2][0] += av.z * b0; acc[2][1] += av.z * b1;
            acc[3][0] += av.w * b0; acc[3][1] += av.w * b1;
        }
    }
    __syncthreads();
    float* Ct = sm;  // 64x17
#pragma unroll
    for (int i = 0; i < 4; i++)
#pragma unroll
        for (int j = 0; j < 2; j++)
            Ct[(ty * 4 + i) * 17 + tx * 2 + j] = acc[i][j] + bkp[h * 16 + tx * 2 + j];
    __syncthreads();
    if (tid < 64) {
        int j = j0 + tid;
        if (j < NWN) {
            const float* qp = g_qp + (b * 8 + h) * 16;
            float ss = 0.f, dt = 0.f;
            for (int c = 0; c < 16; c++) {
                float v = Ct[tid * 17 + c];
                ss += v * v; dt += qp[c] * v;
            }
            g_d3[(size_t)(b * 8 + h) * NS + j] = dt / fmaxf(sqrtf(ss), 1e-12f);
        }
    }
}

// ---- tn: banded correlation : grid(48,8,8), 128 thr, conflict-free Ks stride 37 ----
__global__ void __launch_bounds__(128) tn_kernel() {
    int j0 = blockIdx.x * 128, h = blockIdx.y, b = blockIdx.z;
    int bh = b * 8 + h, tid = threadIdx.x;
    __shared__ float qs[32 * 64];
    __shared__ float Ks[159 * 37];
    for (int u = tid; u < 512; u += 128)
        ((float4*)qs)[u] = ((const float4*)(g_Qhat + bh * 2048))[u];
    float acc = 0.f;
    const float* kb = g_Khat + (size_t)bh * NS * 64;
    for (int p = 0; p < 2; p++) {
        __syncthreads();
        for (int v = tid; v < 159 * 8; v += 128) {
            int u = v >> 3, c4 = (v & 7) * 4;
            int s = j0 + u;
            float4 val = make_float4(0.f, 0.f, 0.f, 0.f);
            if (s < NS) val = *(const float4*)(kb + (size_t)s * 64 + p * 32 + c4);
            Ks[u * 37 + c4 + 0] = val.x; Ks[u * 37 + c4 + 1] = val.y;
            Ks[u * 37 + c4 + 2] = val.z; Ks[u * 37 + c4 + 3] = val.w;
        }
        __syncthreads();
#pragma unroll 4
        for (int m = 0; m < 32; m++) {
            const float* qrow = qs + m * 64 + p * 32;
            const float* krow = Ks + (tid + m) * 37;
#pragma unroll
            for (int c = 0; c < 8; c++) {
                acc += qrow[c * 4 + 0] * krow[c * 4 + 0] + qrow[c * 4 + 1] * krow[c * 4 + 1]
                     + qrow[c * 4 + 2] * krow[c * 4 + 2] + qrow[c * 4 + 3] * krow[c * 4 + 3];
            }
        }
    }
    int j = j0 + tid;
    if (j < NWN) g_tn[(size_t)bh * NS + j] = acc * (1.0f / 32.0f);
}

// ---- softmax over Wn : grid(64), 256 thr ----
__global__ void __launch_bounds__(256) softmax_kernel(const float* __restrict__ w,
                                                      const float* __restrict__ wa,
                                                      const float* __restrict__ wp) {
    int bh = blockIdx.x, tid = threadIdx.x;
    float w0 = w[0], w1 = wa[0], w2 = wp[0];
    size_t base = (size_t)bh * NS;
    __shared__ float red[256];
    float mx = -1e30f;
    for (int j = tid; j < NWN; j += 256) {
        float z = w0 * g_tn[base + j] + w1 * g_d2[base + j] + w2 * g_d3[base + j];
        g_attn[base + j] = z;
        mx = fmaxf(mx, z);
    }
    red[tid] = mx; __syncthreads();
    for (int o = 128; o; o >>= 1) { if (tid < o) red[tid] = fmaxf(red[tid], red[tid + o]); __syncthreads(); }
    mx = red[0]; __syncthreads();
    float sum = 0.f;
    for (int j = tid; j < NWN; j += 256) {
        float e = __expf(g_attn[base + j] - mx);
        g_attn[base + j] = e;
        sum += e;
    }
    red[tid] = sum; __syncthreads();
    for (int o = 128; o; o >>= 1) { if (tid < o) red[tid] += red[tid + o]; __syncthreads(); }
    float inv = 1.f / red[0];
    __syncthreads();
    for (int j = tid; j < NWN; j += 256) g_attn[base + j] *= inv;
    __syncthreads();
    if (tid == 0) g_alast[bh] = g_attn[base + NWN - 1];
}

// ---- ctx partial: attn-weighted sum of x rows : grid(12,8), 512 thr ----
__global__ void __launch_bounds__(512) ctxp_kernel(const float* __restrict__ mem) {
    int wc = blockIdx.x, b = blockIdx.y, tid = threadIdx.x;
    __shared__ float at[8 * 512];
    int w0 = wc * 512;
    for (int u = tid; u < 4096; u += 512) {
        int h = u >> 9, ww = u & 511;
        int w = w0 + ww;
        at[h * 512 + ww] = (w < NWN - 1) ? g_attn[(size_t)(b * 8 + h) * NS + w] : 0.f;
    }
    __syncthreads();
    float acc[8] = {};
    const float* mb = mem + ((size_t)b * NSM1 + 31 + w0) * 512 + tid;
    int wlim = (NWN - 1) - w0; if (wlim > 512) wlim = 512;
    for (int ww = 0; ww < wlim; ww++) {
        float x = mb[(size_t)ww * 512];
#pragma unroll
        for (int h2 = 0; h2 < 8; h2++) acc[h2] += at[h2 * 512 + ww] * x;
    }
#pragma unroll
    for (int h2 = 0; h2 < 8; h2++)
        g_ctxp[(((b * NWC + wc) * 8 + h2) << 9) + tid] = acc[h2];
}

// ---- hist: reduce ctx partials, project through WvM : grid(8b,8h), 256 thr ----
__global__ void __launch_bounds__(256) hist_kernel(const float* __restrict__ bv) {
    int b = blockIdx.x, h = blockIdx.y, tid = threadIdx.x;
    __shared__ float ctxs[512];
    __shared__ float red[256];
    for (int d = tid; d < 512; d += 256) {
        float s = 0.f;
        for (int wc = 0; wc < NWC; wc++)
            s += g_ctxp[(((b * NWC + wc) * 8 + h) << 9) + d];
        ctxs[d] = s;
    }
    __syncthreads();
    int kk = tid >> 2, q = (tid & 3) * 128;
    const float* wr = g_WvM + (h * 64 + kk) * 512 + q;
    float acc = 0.f;
    for (int d = 0; d < 128; d += 4) {
        float4 wv = *(const float4*)(wr + d);
        acc += wv.x * ctxs[q + d] + wv.y * ctxs[q + d + 1] + wv.z * ctxs[q + d + 2] + wv.w * ctxs[q + d + 3];
    }
    red[tid] = acc;
    __syncthreads();
    if (tid < 64) {
        float a1 = 1.0f - g_alast[b * 8 + h];
        float s = red[tid * 4] + red[tid * 4 + 1] + red[tid * 4 + 2] + red[tid * 4 + 3];
        g_hist[(b * 8 + h) * 64 + tid] = s + bv[h * 64 + tid] * a1;
    }
}

// ---- GRU gi precompute : grid(31,8), 192 thr ----
__global__ void gi_kernel(const float* __restrict__ mem, const float* __restrict__ W_ih,
                          const float* __restrict__ b_ih) {
    int t = blockIdx.x, b = blockIdx.y, j = threadIdx.x;
    const float* xr = mem + ((size_t)b * NSM1 + 6112 + t) * 512;
    const float* wr = W_ih + j * 512;
    float acc = b_ih[j];
    for (int d = 0; d < 512; d += 4) {
        float4 xv = *(const float4*)(xr + d);
        float4 wv = *(const float4*)(wr + d);
        acc += xv.x * wv.x + xv.y * wv.y + xv.z * wv.z + xv.w * wv.w;
    }
    g_GI[(t * 8 + b) * 192 + j] = acc;
}

// ---- GRU scan : 1 block, 512 thr ----
__global__ void __launch_bounds__(512) scan_kernel(const float* __restrict__ W_hh,
                                                   const float* __restrict__ b_hh) {
    int tid = threadIdx.x;
    int b = tid >> 6, kk = tid & 63;
    __shared__ float hs[8 * 64];
    hs[tid] = 0.f;
    __syncthreads();
    float bhr = b_hh[kk], bhz = b_hh[64 + kk], bhn = b_hh[128 + kk];
    const float* wr = W_hh + kk * 64;
    const float* wz = W_hh + (64 + kk) * 64;
    const float* wn = W_hh + (128 + kk) * 64;
    for (int t = 0; t < 31; t++) {
        float hr = bhr, hz = bhz, hn = bhn;
        const float* hb = hs + b * 64;
#pragma unroll 8
        for (int e = 0; e < 64; e++) {
            float he = hb[e];
            hr += wr[e] * he; hz += wz[e] * he; hn += wn[e] * he;
        }
        const float* gi = g_GI + (t * 8 + b) * 192;
        float r = 1.f / (1.f + __expf(-(gi[kk] + hr)));
        float z = 1.f / (1.f + __expf(-(gi[64 + kk] + hz)));
        float nst = tanhf(gi[128 + kk] + r * hn);
        float hold = hb[kk];
        float hnew = (1.f - z) * nst + z * hold;
        __syncthreads();
        hs[tid] = hnew;
        __syncthreads();
    }
    g_res[tid] = hs[tid];
}

// ---- final output : grid(8), 512 thr ----
__global__ void __launch_bounds__(512) final_kernel(const float* __restrict__ xpre,
                                                    const float* __restrict__ bO,
                                                    float* __restrict__ out) {
    int b = blockIdx.x, tid = threadIdx.x;
    __shared__ float det[512];
    {
        int h = tid >> 6, kk = tid & 63;
        det[tid] = g_hist[(b * 8 + h) * 64 + kk] + g_alast[b * 8 + h] * g_res[b * 64 + kk];
    }
    __syncthreads();
    float acc = 0.f;
    for (int e = 0; e < 512; e++) acc += det[e] * g_WOMt[e * 512 + tid];
    out[b * 512 + tid] = xpre[b * 512 + tid] + acc + bO[tid];
}

extern "C" void kernel_launch(void* const* d_in, const int* in_sizes, int n_in,
                              void* d_out, int out_size) {
    const float* mem  = (const float*)d_in[0];
    const float* xpre = (const float*)d_in[1];
    const float* aux  = (const float*)d_in[2];
    const float* pos  = (const float*)d_in[3];
    const float* Wq   = (const float*)d_in[4];
    const float* bq   = (const float*)d_in[5];
    const float* Wk   = (const float*)d_in[6];
    const float* bk   = (const float*)d_in[7];
    const float* Wv   = (const float*)d_in[8];
    const float* bv   = (const float*)d_in[9];
    const float* Wqa  = (const float*)d_in[10];
    const float* bqa  = (const float*)d_in[11];
    const float* Wka  = (const float*)d_in[12];
    const float* bka  = (const float*)d_in[13];
    const float* Wqp  = (const float*)d_in[14];
    const float* bqp  = (const float*)d_in[15];
    const float* Wkp  = (const float*)d_in[16];
    const float* bkp  = (const float*)d_in[17];
    const float* W_ih = (const float*)d_in[18];
    const float* W_hh = (const float*)d_in[19];
    const float* b_ih = (const float*)d_in[20];
    const float* b_hh = (const float*)d_in[21];
    const float* WO   = (const float*)d_in[22];
    const float* bO   = (const float*)d_in[23];
    const float* w    = (const float*)d_in[24];
    const float* wa   = (const float*)d_in[25];
    const float* wp   = (const float*)d_in[26];
    const int*   G    = (const int*)d_in[27];
    float* out = (float*)d_out;

    // Reordered so the single ncu-profiled launch lands on kproj.
    prep_kernel<<<(512 * 512 + 255) / 256, 256>>>(Wk, Wq, Wv, WO, G);
    qa_kernel<<<8, 256>>>(aux, Wqa, bqa);
    qp_kernel<<<8, 128>>>(pos, Wqp, bqp);
    kproj_kernel<<<dim3(48, 4, 8), 256>>>(mem, xpre, bk);
    qproj_kernel<<<dim3(8, 8), 256>>>(mem, xpre, bq);
    dot2_kernel<<<dim3(96, 8, 8), 256>>>(aux, Wka, bka);
    dot3_kernel<<<dim3(96, 8, 8), 128>>>(pos, Wkp, bkp);
    tn_kernel<<<dim3(48, 8, 8), 128>>>();
    softmax_kernel<<<64, 256>>>(w, wa, wp);
    ctxp_kernel<<<dim3(NWC, 8), 512>>>(mem);
    hist_kernel<<<dim3(8, 8), 256>>>(bv);
    gi_kernel<<<dim3(31, 8), 192>>>(mem, W_ih, b_ih);
    scan_kernel<<<1, 512>>>(W_hh, b_hh);
    final_kernel<<<8, 512>>>(xpre, bO, out);
}

// round 8
// speedup vs baseline: 1.6695x; 1.0553x over previous
#include <cuda_runtime.h>
#include <math.h>

#define NB 8
#define NH 8
#define NS 6144
#define NSM1 6143
#define NDM 512
#define NDK 64
#define NWN 6113
#define NM 32
#define NWC 12

__device__ float g_WkM[512 * 512];
__device__ float g_WqM[512 * 512];
__device__ float g_WvM[512 * 512];
__device__ float g_WOMt[512 * 512];
__device__ float g_Khat[(size_t)NB * NH * NS * NDK];
__device__ float g_Qhat[NB * NH * NM * NDK];
__device__ float g_qa[NB * NH * 32];
__device__ float g_qp[NB * NH * 16];
__device__ float g_tn[(size_t)NB * NH * NS];
__device__ float g_d2[(size_t)NB * NH * NS];
__device__ float g_d3[(size_t)NB * NH * NS];
__device__ float g_attn[(size_t)NB * NH * NS];
__device__ float g_alast[NB * NH];
__device__ float g_ctxp[NB * NWC * NH * NDM];
__device__ float g_hist[NB * NH * NDK];
__device__ float g_GI[31 * NB * 192];
__device__ float g_res[NB * NDK];

// ---- masked weights ----
__global__ void prep_kernel(const float* __restrict__ Wk, const float* __restrict__ Wq,
                            const float* __restrict__ Wv, const float* __restrict__ WO,
                            const int* __restrict__ G) {
    int i = blockIdx.x * blockDim.x + threadIdx.x;
    if (i >= 512 * 512) return;
    int row = i >> 9, d = i & 511;
    float gm = (float)G[(row & 63) * 64 + (d & 63)];
    g_WkM[i] = Wk[i] * gm;
    g_WqM[i] = Wq[i] * gm;
    g_WvM[i] = Wv[i] * gm;
    float gm2 = (float)G[(d & 63) * 64 + (row & 63)];
    g_WOMt[i] = WO[d * 512 + row] * gm2;  // [e][d] = WO[d][e]*mask
}

// ---- K projection, all heads batched: grid(48,4,8), 256 thr, 128x128 tile ----
__global__ void __launch_bounds__(256) kproj_kernel(const float* __restrict__ mem,
                                                    const float* __restrict__ xpre,
                                                    const float* __restrict__ bk) {
    __shared__ __align__(16) float As[32 * 132];
    __shared__ __align__(16) float Bs[32 * 132];
    int s0 = blockIdx.x * 128, n0 = blockIdx.y * 128, b = blockIdx.z;
    int tid = threadIdx.x;
    int ty = tid >> 4, tx = tid & 15;
    float acc[8][8] = {};
    for (int d0 = 0; d0 < 512; d0 += 32) {
        __syncthreads();
#pragma unroll
        for (int it = 0; it < 4; it++) {
            int idx = it * 256 + tid;
            int rr = idx >> 3, kq = (idx & 7) * 4;
            int s = s0 + rr;
            const float* src = (s < NSM1) ? (mem + ((size_t)b * NSM1 + s) * 512 + d0 + kq)
                                          : (xpre + b * 512 + d0 + kq);
            float4 v = *(const float4*)src;
            As[(kq + 0) * 132 + rr] = v.x; As[(kq + 1) * 132 + rr] = v.y;
            As[(kq + 2) * 132 + rr] = v.z; As[(kq + 3) * 132 + rr] = v.w;
            float4 wv = *(const float4*)(g_WkM + (size_t)(n0 + rr) * 512 + d0 + kq);
            Bs[(kq + 0) * 132 + rr] = wv.x; Bs[(kq + 1) * 132 + rr] = wv.y;
            Bs[(kq + 2) * 132 + rr] = wv.z; Bs[(kq + 3) * 132 + rr] = wv.w;
        }
        __syncthreads();
#pragma unroll
        for (int kk = 0; kk < 32; kk++) {
            float4 a0 = *(const float4*)&As[kk * 132 + ty * 4];
            float4 a1 = *(const float4*)&As[kk * 132 + 64 + ty * 4];
            float4 b0 = *(const float4*)&Bs[kk * 132 + tx * 4];
            float4 b1 = *(const float4*)&Bs[kk * 132 + 64 + tx * 4];
            float ar[8] = {a0.x, a0.y, a0.z, a0.w, a1.x, a1.y, a1.z, a1.w};
            float br[8] = {b0.x, b0.y, b0.z, b0.w, b1.x, b1.y, b1.z, b1.w};
#pragma unroll
            for (int i = 0; i < 8; i++)
#pragma unroll
                for (int j = 0; j < 8; j++) acc[i][j] += ar[i] * br[j];
        }
    }
    float bias[8];
#pragma unroll
    for (int j = 0; j < 4; j++) {
        bias[j] = bk[n0 + tx * 4 + j];
        bias[4 + j] = bk[n0 + 64 + tx * 4 + j];
    }
    int h0 = n0 >> 6;
#pragma unroll
    for (int i = 0; i < 8; i++) {
        int r = (i < 4) ? (ty * 4 + i) : (64 + ty * 4 + (i - 4));
        int s = s0 + r;
        float v[8];
        float ss0 = 0.f, ss1 = 0.f;
#pragma unroll
        for (int j = 0; j < 8; j++) {
            v[j] = acc[i][j] + bias[j];
            if (j < 4) ss0 += v[j] * v[j]; else ss1 += v[j] * v[j];
        }
#pragma unroll
        for (int o = 8; o; o >>= 1) {
            ss0 += __shfl_xor_sync(0xffffffffu, ss0, o);
            ss1 += __shfl_xor_sync(0xffffffffu, ss1, o);
        }
        float i0 = 1.0f / fmaxf(sqrtf(ss0), 1e-12f);
        float i1 = 1.0f / fmaxf(sqrtf(ss1), 1e-12f);
        float* d0p = g_Khat + (((size_t)(b * 8 + h0)) * NS + s) * 64 + tx * 4;
        float* d1p = g_Khat + (((size_t)(b * 8 + h0 + 1)) * NS + s) * 64 + tx * 4;
        *(float4*)d0p = make_float4(v[0] * i0, v[1] * i0, v[2] * i0, v[3] * i0);
        *(float4*)d1p = make_float4(v[4] * i1, v[5] * i1, v[6] * i1, v[7] * i1);
    }
}

// ---- Q projection (last 32 rows) : grid(8h,8b), 256 thr ----
__global__ void __launch_bounds__(256) qproj_kernel(const float* __restrict__ mem,
                                                    const float* __restrict__ xpre,
                                                    const float* __restrict__ bq) {
    int h = blockIdx.x, b = blockIdx.y, tid = threadIdx.x;
    int m = tid >> 3, cg = (tid & 7) * 8;
    float acc[8] = {};
    int s = 6112 + m;
    const float* xr = (s < NSM1) ? (mem + ((size_t)b * NSM1 + s) * 512) : (xpre + b * 512);
    const float* wb = g_WqM + (h * 64 + cg) * 512;
    for (int d = 0; d < 512; d += 4) {
        float4 xv = *(const float4*)(xr + d);
#pragma unroll
        for (int c = 0; c < 8; c++) {
            float4 wv = *(const float4*)(wb + c * 512 + d);
            acc[c] += xv.x * wv.x + xv.y * wv.y + xv.z * wv.z + xv.w * wv.w;
        }
    }
    __shared__ float qs[32 * 65];
#pragma unroll
    for (int c = 0; c < 8; c++) qs[m * 65 + cg + c] = acc[c] + bq[h * 64 + cg + c];
    __syncthreads();
    if (tid < 32) {
        float ss = 0.f;
        for (int c = 0; c < 64; c++) { float v = qs[tid * 65 + c]; ss += v * v; }
        float inv = 1.f / fmaxf(sqrtf(ss), 1e-12f);
        float* dst = g_Qhat + ((b * 8 + h) * 32 + tid) * 64;
        for (int c = 0; c < 64; c++) dst[c] = qs[tid * 65 + c] * inv;
    }
}

// ---- qa_last, qp_last ----
__global__ void qa_kernel(const float* __restrict__ aux, const float* __restrict__ Wqa,
                          const float* __restrict__ bqa) {
    int b = blockIdx.x, tid = threadIdx.x;
    int h = tid >> 5, c = tid & 31;
    const float* row = aux + ((size_t)b * NS + NS - 1) * 256;
    const float* wr = Wqa + (h * 32 + c) * 256;
    float acc = bqa[h * 32 + c];
    for (int a = 0; a < 256; a += 4) {
        float4 xv = *(const float4*)(row + a);
        float4 wv = *(const float4*)(wr + a);
        acc += xv.x * wv.x + xv.y * wv.y + xv.z * wv.z + xv.w * wv.w;
    }
    float ss = acc * acc;
#pragma unroll
    for (int o = 16; o; o >>= 1) ss += __shfl_xor_sync(0xffffffffu, ss, o);
    g_qa[(b * 8 + h) * 32 + c] = acc / fmaxf(sqrtf(ss), 1e-12f);
}

__global__ void qp_kernel(const float* __restrict__ pos, const float* __restrict__ Wqp,
                          const float* __restrict__ bqp) {
    int b = blockIdx.x, tid = threadIdx.x;
    int h = tid >> 4, c = tid & 15;
    const float* row = pos + ((size_t)b * NS + NS - 1) * 128;
    const float* wr = Wqp + (h * 16 + c) * 128;
    float acc = bqp[h * 16 + c];
    for (int a = 0; a < 128; a += 4) {
        float4 xv = *(const float4*)(row + a);
        float4 wv = *(const float4*)(wr + a);
        acc += xv.x * wv.x + xv.y * wv.y + xv.z * wv.z + xv.w * wv.w;
    }
    float ss = acc * acc;
#pragma unroll
    for (int o = 8; o; o >>= 1) ss += __shfl_xor_sync(0xffffffffu, ss, o);
    g_qp[(b * 8 + h) * 16 + c] = acc / fmaxf(sqrtf(ss), 1e-12f);
}

// ---- dot2 batched: C = aux @ Wka_all^T, per-head norm+dot epilogue ----
// grid(48, 2, 8), 256 thr, 128x128 tile, K=256
__global__ void __launch_bounds__(256) dot2_kernel(const float* __restrict__ aux,
                                                   const float* __restrict__ Wka,
                                                   const float* __restrict__ bka) {
    __shared__ __align__(16) float As[32 * 132];
    __shared__ __align__(16) float Bs[32 * 132];
    int j0 = blockIdx.x * 128, n0 = blockIdx.y * 128, b = blockIdx.z;
    int tid = threadIdx.x;
    int ty = tid >> 4, tx = tid & 15;
    float acc[8][8] = {};
    for (int d0 = 0; d0 < 256; d0 += 32) {
        __syncthreads();
#pragma unroll
        for (int it = 0; it < 4; it++) {
            int idx = it * 256 + tid;
            int rr = idx >> 3, kq = (idx & 7) * 4;
            int j = j0 + rr;
            float4 v = make_float4(0.f, 0.f, 0.f, 0.f);
            if (j < NWN) v = *(const float4*)(aux + ((size_t)b * NS + 31 + j) * 256 + d0 + kq);
            As[(kq + 0) * 132 + rr] = v.x; As[(kq + 1) * 132 + rr] = v.y;
            As[(kq + 2) * 132 + rr] = v.z; As[(kq + 3) * 132 + rr] = v.w;
            float4 wv = *(const float4*)(Wka + (size_t)(n0 + rr) * 256 + d0 + kq);
            Bs[(kq + 0) * 132 + rr] = wv.x; Bs[(kq + 1) * 132 + rr] = wv.y;
            Bs[(kq + 2) * 132 + rr] = wv.z; Bs[(kq + 3) * 132 + rr] = wv.w;
        }
        __syncthreads();
#pragma unroll
        for (int kk = 0; kk < 32; kk++) {
            float4 a0 = *(const float4*)&As[kk * 132 + ty * 4];
            float4 a1 = *(const float4*)&As[kk * 132 + 64 + ty * 4];
            float4 b0 = *(const float4*)&Bs[kk * 132 + tx * 4];
            float4 b1 = *(const float4*)&Bs[kk * 132 + 64 + tx * 4];
            float ar[8] = {a0.x, a0.y, a0.z, a0.w, a1.x, a1.y, a1.z, a1.w};
            float br[8] = {b0.x, b0.y, b0.z, b0.w, b1.x, b1.y, b1.z, b1.w};
#pragma unroll
            for (int i = 0; i < 8; i++)
#pragma unroll
                for (int j = 0; j < 8; j++) acc[i][j] += ar[i] * br[j];
        }
    }
    // epilogue: heads are 32-col groups. half0 head = n0/32 + (tx>>3); half1 = +2.
    int hA = (n0 >> 5) + (tx >> 3);
    int hB = hA + 2;
    const float* qaA = g_qa + (b * 8 + hA) * 32;
    const float* qaB = g_qa + (b * 8 + hB) * 32;
    float biasA[4], biasB[4];
#pragma unroll
    for (int j = 0; j < 4; j++) {
        biasA[j] = bka[n0 + tx * 4 + j];
        biasB[j] = bka[n0 + 64 + tx * 4 + j];
    }
    int c32 = (tx & 7) * 4;
#pragma unroll
    for (int i = 0; i < 8; i++) {
        int r = (i < 4) ? (ty * 4 + i) : (64 + ty * 4 + (i - 4));
        int jrow = j0 + r;
        float ss0 = 0.f, dt0 = 0.f, ss1 = 0.f, dt1 = 0.f;
#pragma unroll
        for (int j = 0; j < 4; j++) {
            float v0 = acc[i][j] + biasA[j];
            float v1 = acc[i][4 + j] + biasB[j];
            ss0 += v0 * v0; dt0 += qaA[c32 + j] * v0;
            ss1 += v1 * v1; dt1 += qaB[c32 + j] * v1;
        }
#pragma unroll
        for (int o = 1; o < 8; o <<= 1) {
            ss0 += __shfl_xor_sync(0xffffffffu, ss0, o);
            dt0 += __shfl_xor_sync(0xffffffffu, dt0, o);
            ss1 += __shfl_xor_sync(0xffffffffu, ss1, o);
            dt1 += __shfl_xor_sync(0xffffffffu, dt1, o);
        }
        if ((tx & 7) == 0 && jrow < NWN) {
            g_d2[(size_t)(b * 8 + hA) * NS + jrow] = dt0 / fmaxf(sqrtf(ss0), 1e-12f);
            g_d2[(size_t)(b * 8 + hB) * NS + jrow] = dt1 / fmaxf(sqrtf(ss1), 1e-12f);
        }
    }
}

// ---- dot3 batched: C = pos @ Wkp_all^T : grid(48,1,8), 256 thr, 128x128, K=128 ----
__global__ void __launch_bounds__(256) dot3_kernel(const float* __restrict__ pos,
                                                   const float* __restrict__ Wkp,
                                                   const float* __restrict__ bkp) {
    __shared__ __align__(16) float As[32 * 132];
    __shared__ __align__(16) float Bs[32 * 132];
    int j0 = blockIdx.x * 128, b = blockIdx.z;
    int tid = threadIdx.x;
    int ty = tid >> 4, tx = tid & 15;
    float acc[8][8] = {};
    for (int d0 = 0; d0 < 128; d0 += 32) {
        __syncthreads();
#pragma unroll
        for (int it = 0; it < 4; it++) {
            int idx = it * 256 + tid;
            int rr = idx >> 3, kq = (idx & 7) * 4;
            int j = j0 + rr;
            float4 v = make_float4(0.f, 0.f, 0.f, 0.f);
            if (j < NWN) v = *(const float4*)(pos + ((size_t)b * NS + 31 + j) * 128 + d0 + kq);
            As[(kq + 0) * 132 + rr] = v.x; As[(kq + 1) * 132 + rr] = v.y;
            As[(kq + 2) * 132 + rr] = v.z; As[(kq + 3) * 132 + rr] = v.w;
            float4 wv = *(const float4*)(Wkp + (size_t)rr * 128 + d0 + kq);
            Bs[(kq + 0) * 132 + rr] = wv.x; Bs[(kq + 1) * 132 + rr] = wv.y;
            Bs[(kq + 2) * 132 + rr] = wv.z; Bs[(kq + 3) * 132 + rr] = wv.w;
        }
        __syncthreads();
#pragma unroll
        for (int kk = 0; kk < 32; kk++) {
            float4 a0 = *(const float4*)&As[kk * 132 + ty * 4];
            float4 a1 = *(const float4*)&As[kk * 132 + 64 + ty * 4];
            float4 b0 = *(const float4*)&Bs[kk * 132 + tx * 4];
            float4 b1 = *(const float4*)&Bs[kk * 132 + 64 + tx * 4];
            float ar[8] = {a0.x, a0.y, a0.z, a0.w, a1.x, a1.y, a1.z, a1.w};
            float br[8] = {b0.x, b0.y, b0.z, b0.w, b1.x, b1.y, b1.z, b1.w};
#pragma unroll
            for (int i = 0; i < 8; i++)
#pragma unroll
                for (int j = 0; j < 8; j++) acc[i][j] += ar[i] * br[j];
        }
    }
    // heads are 16-col groups (4 lanes each). half0 head = tx>>2; half1 = 4+(tx>>2).
    int hA = tx >> 2;
    int hB = hA + 4;
    const float* qpA = g_qp + (b * 8 + hA) * 16;
    const float* qpB = g_qp + (b * 8 + hB) * 16;
    float biasA[4], biasB[4];
#pragma unroll
    for (int j = 0; j < 4; j++) {
        biasA[j] = bkp[tx * 4 + j];
        biasB[j] = bkp[64 + tx * 4 + j];
    }
    int c16 = (tx & 3) * 4;
#pragma unroll
    for (int i = 0; i < 8; i++) {
        int r = (i < 4) ? (ty * 4 + i) : (64 + ty * 4 + (i - 4));
        int jrow = j0 + r;
        float ss0 = 0.f, dt0 = 0.f, ss1 = 0.f, dt1 = 0.f;
#pragma unroll
        for (int j = 0; j < 4; j++) {
            float v0 = acc[i][j] + biasA[j];
            float v1 = acc[i][4 + j] + biasB[j];
            ss0 += v0 * v0; dt0 += qpA[c16 + j] * v0;
            ss1 += v1 * v1; dt1 += qpB[c16 + j] * v1;
        }
#pragma unroll
        for (int o = 1; o < 4; o <<= 1) {
            ss0 += __shfl_xor_sync(0xffffffffu, ss0, o);
            dt0 += __shfl_xor_sync(0xffffffffu, dt0, o);
            ss1 += __shfl_xor_sync(0xffffffffu, ss1, o);
            dt1 += __shfl_xor_sync(0xffffffffu, dt1, o);
        }
        if ((tx & 3) == 0 && jrow < NWN) {
            g_d3[(size_t)(b * 8 + hA) * NS + jrow] = dt0 / fmaxf(sqrtf(ss0), 1e-12f);
            g_d3[(size_t)(b * 8 + hB) * NS + jrow] = dt1 / fmaxf(sqrtf(ss1), 1e-12f);
        }
    }
}

// ---- tn: banded correlation : grid(48,8,8), 128 thr, conflict-free stride 37 ----
__global__ void __launch_bounds__(128) tn_kernel() {
    int j0 = blockIdx.x * 128, h = blockIdx.y, b = blockIdx.z;
    int bh = b * 8 + h, tid = threadIdx.x;
    __shared__ float qs[32 * 64];
    __shared__ float Ks[159 * 37];
    for (int u = tid; u < 512; u += 128)
        ((float4*)qs)[u] = ((const float4*)(g_Qhat + bh * 2048))[u];
    float acc = 0.f;
    const float* kb = g_Khat + (size_t)bh * NS * 64;
    for (int p = 0; p < 2; p++) {
        __syncthreads();
        for (int v = tid; v < 159 * 8; v += 128) {
            int u = v >> 3, c4 = (v & 7) * 4;
            int s = j0 + u;
            float4 val = make_float4(0.f, 0.f, 0.f, 0.f);
            if (s < NS) val = *(const float4*)(kb + (size_t)s * 64 + p * 32 + c4);
            Ks[u * 37 + c4 + 0] = val.x; Ks[u * 37 + c4 + 1] = val.y;
            Ks[u * 37 + c4 + 2] = val.z; Ks[u * 37 + c4 + 3] = val.w;
        }
        __syncthreads();
#pragma unroll 4
        for (int m = 0; m < 32; m++) {
            const float* qrow = qs + m * 64 + p * 32;
            const float* krow = Ks + (tid + m) * 37;
#pragma unroll
            for (int c = 0; c < 8; c++) {
                acc += qrow[c * 4 + 0] * krow[c * 4 + 0] + qrow[c * 4 + 1] * krow[c * 4 + 1]
                     + qrow[c * 4 + 2] * krow[c * 4 + 2] + qrow[c * 4 + 3] * krow[c * 4 + 3];
            }
        }
    }
    int j = j0 + tid;
    if (j < NWN) g_tn[(size_t)bh * NS + j] = acc * (1.0f / 32.0f);
}

// ---- softmax over Wn : grid(64), 256 thr ----
__global__ void __launch_bounds__(256) softmax_kernel(const float* __restrict__ w,
                                                      const float* __restrict__ wa,
                                                      const float* __restrict__ wp) {
    int bh = blockIdx.x, tid = threadIdx.x;
    float w0 = w[0], w1 = wa[0], w2 = wp[0];
    size_t base = (size_t)bh * NS;
    __shared__ float red[256];
    float mx = -1e30f;
    for (int j = tid; j < NWN; j += 256) {
        float z = w0 * g_tn[base + j] + w1 * g_d2[base + j] + w2 * g_d3[base + j];
        g_attn[base + j] = z;
        mx = fmaxf(mx, z);
    }
    red[tid] = mx; __syncthreads();
    for (int o = 128; o; o >>= 1) { if (tid < o) red[tid] = fmaxf(red[tid], red[tid + o]); __syncthreads(); }
    mx = red[0]; __syncthreads();
    float sum = 0.f;
    for (int j = tid; j < NWN; j += 256) {
        float e = __expf(g_attn[base + j] - mx);
        g_attn[base + j] = e;
        sum += e;
    }
    red[tid] = sum; __syncthreads();
    for (int o = 128; o; o >>= 1) { if (tid < o) red[tid] += red[tid + o]; __syncthreads(); }
    float inv = 1.f / red[0];
    __syncthreads();
    for (int j = tid; j < NWN; j += 256) g_attn[base + j] *= inv;
    __syncthreads();
    if (tid == 0) g_alast[bh] = g_attn[base + NWN - 1];
}

// ---- ctx partial: grid(12,8), 512 thr ----
__global__ void __launch_bounds__(512) ctxp_kernel(const float* __restrict__ mem) {
    int wc = blockIdx.x, b = blockIdx.y, tid = threadIdx.x;
    __shared__ float at[8 * 512];
    int w0 = wc * 512;
    for (int u = tid; u < 4096; u += 512) {
        int h = u >> 9, ww = u & 511;
        int w = w0 + ww;
        at[h * 512 + ww] = (w < NWN - 1) ? g_attn[(size_t)(b * 8 + h) * NS + w] : 0.f;
    }
    __syncthreads();
    float acc[8] = {};
    const float* mb = mem + ((size_t)b * NSM1 + 31 + w0) * 512 + tid;
    int wlim = (NWN - 1) - w0; if (wlim > 512) wlim = 512;
    for (int ww = 0; ww < wlim; ww++) {
        float x = mb[(size_t)ww * 512];
#pragma unroll
        for (int h2 = 0; h2 < 8; h2++) acc[h2] += at[h2 * 512 + ww] * x;
    }
#pragma unroll
    for (int h2 = 0; h2 < 8; h2++)
        g_ctxp[(((b * NWC + wc) * 8 + h2) << 9) + tid] = acc[h2];
}

// ---- hist : grid(8b,8h), 256 thr ----
__global__ void __launch_bounds__(256) hist_kernel(const float* __restrict__ bv) {
    int b = blockIdx.x, h = blockIdx.y, tid = threadIdx.x;
    __shared__ float ctxs[512];
    __shared__ float red[256];
    for (int d = tid; d < 512; d += 256) {
        float s = 0.f;
        for (int wc = 0; wc < NWC; wc++)
            s += g_ctxp[(((b * NWC + wc) * 8 + h) << 9) + d];
        ctxs[d] = s;
    }
    __syncthreads();
    int kk = tid >> 2, q = (tid & 3) * 128;
    const float* wr = g_WvM + (h * 64 + kk) * 512 + q;
    float acc = 0.f;
    for (int d = 0; d < 128; d += 4) {
        float4 wv = *(const float4*)(wr + d);
        acc += wv.x * ctxs[q + d] + wv.y * ctxs[q + d + 1] + wv.z * ctxs[q + d + 2] + wv.w * ctxs[q + d + 3];
    }
    red[tid] = acc;
    __syncthreads();
    if (tid < 64) {
        float a1 = 1.0f - g_alast[b * 8 + h];
        float s = red[tid * 4] + red[tid * 4 + 1] + red[tid * 4 + 2] + red[tid * 4 + 3];
        g_hist[(b * 8 + h) * 64 + tid] = s + bv[h * 64 + tid] * a1;
    }
}

// ---- GRU gi precompute : grid(31,8), 192 thr ----
__global__ void gi_kernel(const float* __restrict__ mem, const float* __restrict__ W_ih,
                          const float* __restrict__ b_ih) {
    int t = blockIdx.x, b = blockIdx.y, j = threadIdx.x;
    const float* xr = mem + ((size_t)b * NSM1 + 6112 + t) * 512;
    const float* wr = W_ih + j * 512;
    float acc = b_ih[j];
    for (int d = 0; d < 512; d += 4) {
        float4 xv = *(const float4*)(xr + d);
        float4 wv = *(const float4*)(wr + d);
        acc += xv.x * wv.x + xv.y * wv.y + xv.z * wv.z + xv.w * wv.w;
    }
    g_GI[(t * 8 + b) * 192 + j] = acc;
}

// ---- GRU scan : 1 block, 512 thr ----
__global__ void __launch_bounds__(512) scan_kernel(const float* __restrict__ W_hh,
                                                   const float* __restrict__ b_hh) {
    int tid = threadIdx.x;
    int b = tid >> 6, kk = tid & 63;
    __shared__ float hs[8 * 64];
    hs[tid] = 0.f;
    __syncthreads();
    float bhr = b_hh[kk], bhz = b_hh[64 + kk], bhn = b_hh[128 + kk];
    const float* wr = W_hh + kk * 64;
    const float* wz = W_hh + (64 + kk) * 64;
    const float* wn = W_hh + (128 + kk) * 64;
    for (int t = 0; t < 31; t++) {
        float hr = bhr, hz = bhz, hn = bhn;
        const float* hb = hs + b * 64;
#pragma unroll 8
        for (int e = 0; e < 64; e++) {
            float he = hb[e];
            hr += wr[e] * he; hz += wz[e] * he; hn += wn[e] * he;
        }
        const float* gi = g_GI + (t * 8 + b) * 192;
        float r = 1.f / (1.f + __expf(-(gi[kk] + hr)));
        float z = 1.f / (1.f + __expf(-(gi[64 + kk] + hz)));
        float nst = tanhf(gi[128 + kk] + r * hn);
        float hold = hb[kk];
        float hnew = (1.f - z) * nst + z * hold;
        __syncthreads();
        hs[tid] = hnew;
        __syncthreads();
    }
    g_res[tid] = hs[tid];
}

// ---- final output : grid(8), 512 thr ----
__global__ void __launch_bounds__(512) final_kernel(const float* __restrict__ xpre,
                                                    const float* __restrict__ bO,
                                                    float* __restrict__ out) {
    int b = blockIdx.x, tid = threadIdx.x;
    __shared__ float det[512];
    {
        int h = tid >> 6, kk = tid & 63;
        det[tid] = g_hist[(b * 8 + h) * 64 + kk] + g_alast[b * 8 + h] * g_res[b * 64 + kk];
    }
    __syncthreads();
    float acc = 0.f;
    for (int e = 0; e < 512; e++) acc += det[e] * g_WOMt[e * 512 + tid];
    out[b * 512 + tid] = xpre[b * 512 + tid] + acc + bO[tid];
}

extern "C" void kernel_launch(void* const* d_in, const int* in_sizes, int n_in,
                              void* d_out, int out_size) {
    const float* mem  = (const float*)d_in[0];
    const float* xpre = (const float*)d_in[1];
    const float* aux  = (const float*)d_in[2];
    const float* pos  = (const float*)d_in[3];
    const float* Wq   = (const float*)d_in[4];
    const float* bq   = (const float*)d_in[5];
    const float* Wk   = (const float*)d_in[6];
    const float* bk   = (const float*)d_in[7];
    const float* Wv   = (const float*)d_in[8];
    const float* bv   = (const float*)d_in[9];
    const float* Wqa  = (const float*)d_in[10];
    const float* bqa  = (const float*)d_in[11];
    const float* Wka  = (const float*)d_in[12];
    const float* bka  = (const float*)d_in[13];
    const float* Wqp  = (const float*)d_in[14];
    const float* bqp  = (const float*)d_in[15];
    const float* Wkp  = (const float*)d_in[16];
    const float* bkp  = (const float*)d_in[17];
    const float* W_ih = (const float*)d_in[18];
    const float* W_hh = (const float*)d_in[19];
    const float* b_ih = (const float*)d_in[20];
    const float* b_hh = (const float*)d_in[21];
    const float* WO   = (const float*)d_in[22];
    const float* bO   = (const float*)d_in[23];
    const float* w    = (const float*)d_in[24];
    const float* wa   = (const float*)d_in[25];
    const float* wp   = (const float*)d_in[26];
    const int*   G    = (const int*)d_in[27];
    float* out = (float*)d_out;

    prep_kernel<<<(512 * 512 + 255) / 256, 256>>>(Wk, Wq, Wv, WO, G);
    qa_kernel<<<8, 256>>>(aux, Wqa, bqa);
    qp_kernel<<<8, 128>>>(pos, Wqp, bqp);
    kproj_kernel<<<dim3(48, 4, 8), 256>>>(mem, xpre, bk);
    qproj_kernel<<<dim3(8, 8), 256>>>(mem, xpre, bq);
    dot2_kernel<<<dim3(48, 2, 8), 256>>>(aux, Wka, bka);
    dot3_kernel<<<dim3(48, 1, 8), 256>>>(pos, Wkp, bkp);
    tn_kernel<<<dim3(48, 8, 8), 128>>>();
    softmax_kernel<<<64, 256>>>(w, wa, wp);
    ctxp_kernel<<<dim3(NWC, 8), 512>>>(mem);
    hist_kernel<<<dim3(8, 8), 256>>>(bv);
    gi_kernel<<<dim3(31, 8), 192>>>(mem, W_ih, b_ih);
    scan_kernel<<<1, 512>>>(W_hh, b_hh);
    final_kernel<<<8, 512>>>(xpre, bO, out);
}